// round 9
// baseline (speedup 1.0000x reference)
#include <cuda_runtime.h>
#include <cuda_bf16.h>
#include <cstdint>

#define N_S 100000
#define N_C 20000
#define N_L 5000
#define E_U 2000000
#define E_T 500000
#define D_S 64
#define D_C 32
#define D_L 128
#define HDIM 128
#define NLAY 3

#define SCAN_ELEMS 1024
#define NBLK ((N_C + SCAN_ELEMS - 1) / SCAN_ELEMS)   // 20

// ---------------- scratch (static __device__ allocations only) ----------------
__device__ int   g_deg_u[N_C];
__device__ int   g_deg_t[N_C];
__device__ int   g_rp_u[N_C + 1];
__device__ int   g_rp_t[N_C + 1];
__device__ int   g_cur_u[N_C];
__device__ int   g_cur_t[N_C];
__device__ int   g_csr_u[E_U];
__device__ int   g_csr_t[E_T];
__device__ int   g_blksum[2][NBLK];
__device__ int   g_blkoff[2][NBLK];
__device__ float g_mf[N_C * 192];        // [c][0:64]=mean student feat, [64:192]=mean lecture feat
__device__ float g_bu[384];              // b_fs @ Wnu_i  (applies when deg_u>0)
__device__ float g_bl[384];              // b_fl @ Wnt_i  (applies when deg_t>0)
__device__ float g_bsum[384];            // b_u[i] + b_t[i]
__device__ float g_const[N_C * 384];     // per-layer constant terms
__device__ float g_hcA[N_C * HDIM];
__device__ float g_hcB[N_C * HDIM];

// bf16 hi/lo split B operands, transposed to [n][k], zero-padded in k
__device__ __align__(16) __nv_bfloat16 g_BhiF[384 * 192];   // fused neigh weights (K=192)
__device__ __align__(16) __nv_bfloat16 g_BloF[384 * 192];
__device__ __align__(16) __nv_bfloat16 g_BhiW[NLAY * 128 * 128]; // W_self sums (K=128)
__device__ __align__(16) __nv_bfloat16 g_BloW[NLAY * 128 * 128];
__device__ __align__(16) __nv_bfloat16 g_BhiP[128 * 64];    // W_fc^T, K=32 padded to 64
__device__ __align__(16) __nv_bfloat16 g_BloP[128 * 64];

// tags
#define TAG_EXT   0
#define TAG_MF    1
#define TAG_CONST 3
#define TAG_HCA   4
#define TAG_HCB   5
#define TAG_BF    7
#define TAG_BW    8
#define TAG_BP    9

__device__ __forceinline__ const float* resolve_a(int tag, const float* ext) {
    switch (tag) {
        case TAG_MF:  return g_mf;
        case TAG_HCA: return g_hcA;
        case TAG_HCB: return g_hcB;
        default:      return ext;
    }
}
__device__ __forceinline__ float* resolve_cm(int tag, float* ext) {
    switch (tag) {
        case TAG_CONST: return g_const;
        case TAG_HCA:   return g_hcA;
        case TAG_HCB:   return g_hcB;
        default:        return ext;
    }
}
__device__ __forceinline__ void resolve_b(int tag, int off,
                                          const __nv_bfloat16*& bh, const __nv_bfloat16*& bl) {
    switch (tag) {
        case TAG_BW: bh = g_BhiW + off; bl = g_BloW + off; break;
        case TAG_BP: bh = g_BhiP;       bl = g_BloP;       break;
        default:     bh = g_BhiF;       bl = g_BloF;       break;
    }
}

__device__ __forceinline__ uint32_t smem_u32(const void* p) {
    uint32_t a;
    asm("{ .reg .u64 t; cvta.to.shared.u64 t, %1; cvt.u32.u64 %0, t; }" : "=r"(a) : "l"(p));
    return a;
}

#define LDM4(r0, r1, r2, r3, addr) \
    asm volatile("ldmatrix.sync.aligned.m8n8.x4.shared.b16 {%0,%1,%2,%3}, [%4];" \
                 : "=r"(r0), "=r"(r1), "=r"(r2), "=r"(r3) : "r"(addr))

#define MMA16816(c, a, b0, b1) \
    asm volatile("mma.sync.aligned.m16n8k16.row.col.f32.bf16.bf16.f32 " \
                 "{%0,%1,%2,%3}, {%4,%5,%6,%7}, {%8,%9}, {%0,%1,%2,%3};" \
                 : "+f"((c)[0]), "+f"((c)[1]), "+f"((c)[2]), "+f"((c)[3]) \
                 : "r"((a)[0]), "r"((a)[1]), "r"((a)[2]), "r"((a)[3]), "r"(b0), "r"(b1))

__device__ __forceinline__ void split_bf16(float x, __nv_bfloat16& h, __nv_bfloat16& l) {
    h = __float2bfloat16(x);
    l = __float2bfloat16(x - __bfloat162float(h));
}

// ---------------- CSR build ----------------
__global__ void zero_deg_kernel() {
    int i = blockIdx.x * blockDim.x + threadIdx.x;
    if (i < N_C) { g_deg_u[i] = 0; g_deg_t[i] = 0; }
}

__global__ void hist_all_kernel(const int4* __restrict__ und_dst, const int4* __restrict__ tea_dst) {
    int i = blockIdx.x * blockDim.x + threadIdx.x;
    if (i < E_U / 4) {
        int4 d = und_dst[i];
        atomicAdd(&g_deg_u[d.x], 1);
        atomicAdd(&g_deg_u[d.y], 1);
        atomicAdd(&g_deg_u[d.z], 1);
        atomicAdd(&g_deg_u[d.w], 1);
    } else {
        int j = i - E_U / 4;
        if (j < E_T / 4) {
            int4 d = tea_dst[j];
            atomicAdd(&g_deg_t[d.x], 1);
            atomicAdd(&g_deg_t[d.y], 1);
            atomicAdd(&g_deg_t[d.z], 1);
            atomicAdd(&g_deg_t[d.w], 1);
        }
    }
}

__global__ void scan_part_kernel() {
    int rel = blockIdx.y;
    const int* deg = rel ? g_deg_t : g_deg_u;
    int tid = threadIdx.x;
    int base = blockIdx.x * SCAN_ELEMS + tid * 4;
    int s = 0;
#pragma unroll
    for (int j = 0; j < 4; j++)
        if (base + j < N_C) s += deg[base + j];
    __shared__ int sh[256];
    sh[tid] = s;
    __syncthreads();
    for (int off = 128; off > 0; off >>= 1) {
        if (tid < off) sh[tid] += sh[tid + off];
        __syncthreads();
    }
    if (tid == 0) g_blksum[rel][blockIdx.x] = sh[0];
}

__global__ void scan_mid_kernel() {
    int tid = threadIdx.x;
    if (tid < 2) {
        int run = 0;
        for (int b = 0; b < NBLK; b++) {
            g_blkoff[tid][b] = run;
            run += g_blksum[tid][b];
        }
        if (tid) g_rp_t[N_C] = run; else g_rp_u[N_C] = run;
    }
}

__global__ void scan_emit_kernel() {
    int rel = blockIdx.y;
    const int* deg = rel ? g_deg_t : g_deg_u;
    int* rowptr = rel ? g_rp_t : g_rp_u;
    int* cur = rel ? g_cur_t : g_cur_u;
    int tid = threadIdx.x;
    int base = blockIdx.x * SCAN_ELEMS + tid * 4;
    int v[4];
    int s = 0;
#pragma unroll
    for (int j = 0; j < 4; j++) {
        v[j] = (base + j < N_C) ? deg[base + j] : 0;
        s += v[j];
    }
    __shared__ int sh[256];
    sh[tid] = s;
    __syncthreads();
    for (int off = 1; off < 256; off <<= 1) {
        int t = (tid >= off) ? sh[tid - off] : 0;
        __syncthreads();
        sh[tid] += t;
        __syncthreads();
    }
    int excl = ((tid > 0) ? sh[tid - 1] : 0) + g_blkoff[rel][blockIdx.x];
#pragma unroll
    for (int j = 0; j < 4; j++) {
        if (base + j < N_C) {
            rowptr[base + j] = excl;
            cur[base + j] = excl;
            excl += v[j];
        }
    }
}

__global__ void scatter_all_kernel(const int4* __restrict__ und_src, const int4* __restrict__ und_dst,
                                   const int4* __restrict__ tea_src, const int4* __restrict__ tea_dst) {
    int i = blockIdx.x * blockDim.x + threadIdx.x;
    if (i < E_U / 4) {
        int4 d = und_dst[i];
        int4 s = und_src[i];
        g_csr_u[atomicAdd(&g_cur_u[d.x], 1)] = s.x;
        g_csr_u[atomicAdd(&g_cur_u[d.y], 1)] = s.y;
        g_csr_u[atomicAdd(&g_cur_u[d.z], 1)] = s.z;
        g_csr_u[atomicAdd(&g_cur_u[d.w], 1)] = s.w;
    } else {
        int j = i - E_U / 4;
        if (j < E_T / 4) {
            int4 d = tea_dst[j];
            int4 s = tea_src[j];
            g_csr_t[atomicAdd(&g_cur_t[d.x], 1)] = s.x;
            g_csr_t[atomicAdd(&g_cur_t[d.y], 1)] = s.y;
            g_csr_t[atomicAdd(&g_cur_t[d.z], 1)] = s.z;
            g_csr_t[atomicAdd(&g_cur_t[d.w], 1)] = s.w;
        }
    }
}

// ---------------- aggregation ----------------
__global__ void agg_all_kernel(const float* __restrict__ feat_s, const float* __restrict__ feat_l) {
    int w = (blockIdx.x * blockDim.x + threadIdx.x) >> 5;
    int lane = threadIdx.x & 31;
    if (w < N_C) {
        int s0 = g_rp_u[w], s1 = g_rp_u[w + 1];
        float2 a0 = {0.f, 0.f}, a1 = {0.f, 0.f}, a2 = {0.f, 0.f}, a3 = {0.f, 0.f};
        int e = s0;
        for (; e + 4 <= s1; e += 4) {
            int i0 = g_csr_u[e], i1 = g_csr_u[e + 1], i2 = g_csr_u[e + 2], i3 = g_csr_u[e + 3];
            float2 v0 = __ldg((const float2*)(feat_s + (size_t)i0 * D_S) + lane);
            float2 v1 = __ldg((const float2*)(feat_s + (size_t)i1 * D_S) + lane);
            float2 v2 = __ldg((const float2*)(feat_s + (size_t)i2 * D_S) + lane);
            float2 v3 = __ldg((const float2*)(feat_s + (size_t)i3 * D_S) + lane);
            a0.x += v0.x; a0.y += v0.y;
            a1.x += v1.x; a1.y += v1.y;
            a2.x += v2.x; a2.y += v2.y;
            a3.x += v3.x; a3.y += v3.y;
        }
        for (; e < s1; e++) {
            int i0 = g_csr_u[e];
            float2 v0 = __ldg((const float2*)(feat_s + (size_t)i0 * D_S) + lane);
            a0.x += v0.x; a0.y += v0.y;
        }
        float sx = a0.x + a1.x + a2.x + a3.x;
        float sy = a0.y + a1.y + a2.y + a3.y;
        float inv = 1.0f / (float)max(s1 - s0, 1);
        g_mf[(size_t)w * 192 + lane * 2 + 0] = sx * inv;
        g_mf[(size_t)w * 192 + lane * 2 + 1] = sy * inv;
    } else if (w < 2 * N_C) {
        int c = w - N_C;
        int s0 = g_rp_t[c], s1 = g_rp_t[c + 1];
        float4 a0 = {0, 0, 0, 0}, a1 = {0, 0, 0, 0};
        int e = s0;
        for (; e + 2 <= s1; e += 2) {
            int i0 = g_csr_t[e], i1 = g_csr_t[e + 1];
            float4 v0 = __ldg((const float4*)(feat_l + (size_t)i0 * D_L) + lane);
            float4 v1 = __ldg((const float4*)(feat_l + (size_t)i1 * D_L) + lane);
            a0.x += v0.x; a0.y += v0.y; a0.z += v0.z; a0.w += v0.w;
            a1.x += v1.x; a1.y += v1.y; a1.z += v1.z; a1.w += v1.w;
        }
        for (; e < s1; e++) {
            int i0 = g_csr_t[e];
            float4 v0 = __ldg((const float4*)(feat_l + (size_t)i0 * D_L) + lane);
            a0.x += v0.x; a0.y += v0.y; a0.z += v0.z; a0.w += v0.w;
        }
        float sx = a0.x + a1.x, sy = a0.y + a1.y, sz = a0.z + a1.z, sw = a0.w + a1.w;
        float inv = 1.0f / (float)max(s1 - s0, 1);
        float* o = g_mf + (size_t)c * 192 + 64 + lane * 4;
        o[0] = sx * inv; o[1] = sy * inv; o[2] = sz * inv; o[3] = sw * inv;
    }
}

// ---------------- weight prep: fold + transpose + bf16 hi/lo split ----------------
__global__ void prep_kernel(const float* __restrict__ W_fs, const float* __restrict__ b_fs,
                            const float* __restrict__ W_fl, const float* __restrict__ b_fl,
                            const float* __restrict__ Wsu, const float* __restrict__ Wnu,
                            const float* __restrict__ bu_in,
                            const float* __restrict__ Wst, const float* __restrict__ Wnt,
                            const float* __restrict__ bt_in,
                            const float* __restrict__ W_fc) {
    const int nF = 384 * 192;
    const int nB = 384 * 3;
    const int nW = NLAY * 128 * 128;
    const int nP = 128 * 64;
    int idx = blockIdx.x * blockDim.x + threadIdx.x;
    if (idx < nF) {
        int c = idx / 192, r = idx % 192;
        int li = c >> 7, n = c & 127;
        float s = 0.f;
        if (r < 64) {
            const float* wn = Wnu + li * HDIM * HDIM;
            for (int k = 0; k < HDIM; k++) s += W_fs[r * HDIM + k] * wn[k * HDIM + n];
        } else {
            const float* wn = Wnt + li * HDIM * HDIM;
            int rr = r - 64;
            for (int k = 0; k < HDIM; k++) s += W_fl[rr * HDIM + k] * wn[k * HDIM + n];
        }
        __nv_bfloat16 h, l;
        split_bf16(s, h, l);
        g_BhiF[c * 192 + r] = h;
        g_BloF[c * 192 + r] = l;
        return;
    }
    idx -= nF;
    if (idx < nB) {
        int which = idx / 384, q = idx % 384;
        int li = q >> 7, n = q & 127;
        if (which == 0) {
            const float* wn = Wnu + li * HDIM * HDIM;
            float s = 0.f;
            for (int k = 0; k < HDIM; k++) s += b_fs[k] * wn[k * HDIM + n];
            g_bu[q] = s;
        } else if (which == 1) {
            const float* wn = Wnt + li * HDIM * HDIM;
            float s = 0.f;
            for (int k = 0; k < HDIM; k++) s += b_fl[k] * wn[k * HDIM + n];
            g_bl[q] = s;
        } else {
            g_bsum[q] = bu_in[q] + bt_in[q];
        }
        return;
    }
    idx -= nB;
    if (idx < nW) {
        int li = idx / (128 * 128);
        int rem = idx % (128 * 128);
        int n = rem / 128, k = rem % 128;
        float w = Wsu[li * 128 * 128 + k * 128 + n] + Wst[li * 128 * 128 + k * 128 + n];
        __nv_bfloat16 h, l;
        split_bf16(w, h, l);
        g_BhiW[li * 128 * 128 + n * 128 + k] = h;
        g_BloW[li * 128 * 128 + n * 128 + k] = l;
        return;
    }
    idx -= nW;
    if (idx < nP) {
        int n = idx / 64, k = idx % 64;
        float w = (k < D_C) ? W_fc[k * HDIM + n] : 0.f;
        __nv_bfloat16 h, l;
        split_bf16(w, h, l);
        g_BhiP[n * 64 + k] = h;
        g_BloP[n * 64 + k] = l;
        return;
    }
}

// ---------------- mma.sync bf16-split GEMM ----------------
// CTA tile 128x128, 8 warps (4x2), warp tile 32x64, BK=32.
// C = A[128,K](fp32, split on the fly) @ B[n][k](prepped bf16 hi/lo)^T, 3-pass hi/lo.
// epi_mode: 0 = cbuf+alpha+relu (layers), 1 = const-build, 2 = external bias (proj)
#define BK 32
#define SSTR 40   // smem row stride in bf16 elems (80B: conflict-free 8-row ldmatrix)
__global__ __launch_bounds__(256) void mma_gemm_kernel(
    int a_tag, const float* a_ext, int lda, int K, int K_PAD,
    int b_tag, int b_off,
    int c_tag, float* c_ext, int ldc,
    int M,
    int epi_mode, const float* bias_ext, int coff, float alpha, int relu) {
    __shared__ __align__(16) __nv_bfloat16 sAh[128][SSTR];
    __shared__ __align__(16) __nv_bfloat16 sAl[128][SSTR];
    __shared__ __align__(16) __nv_bfloat16 sBh[128][SSTR];
    __shared__ __align__(16) __nv_bfloat16 sBl[128][SSTR];

    int tid = threadIdx.x;
    int wid = tid >> 5;
    int lane = tid & 31;
    int m0 = blockIdx.x * 128;
    int n0 = blockIdx.y * 128;
    int wm = (wid & 3) * 32;   // warp m offset in tile
    int wn = (wid >> 2) * 64;  // warp n offset in tile

    const float* A = resolve_a(a_tag, a_ext);
    float* C = resolve_cm(c_tag, c_ext);
    const __nv_bfloat16 *Bhi, *Blo;
    resolve_b(b_tag, b_off, Bhi, Blo);

    float acc[2][8][4];
#pragma unroll
    for (int mi = 0; mi < 2; mi++)
#pragma unroll
        for (int ni = 0; ni < 8; ni++)
#pragma unroll
            for (int q = 0; q < 4; q++) acc[mi][ni][q] = 0.f;

    int nchunks = (K + BK - 1) / BK;
    for (int kc = 0; kc < nchunks; kc++) {
        // fill A: 128 rows x 8 float4 -> bf16 hi/lo
        for (int idx = tid; idx < 128 * 8; idx += 256) {
            int row = idx >> 3;
            int kl = (idx & 7) << 2;
            int gm = m0 + row;
            float4 av = make_float4(0.f, 0.f, 0.f, 0.f);
            if (gm < M) av = *(const float4*)(A + (size_t)gm * lda + kc * BK + kl);
            __nv_bfloat162 h0, h1, l0, l1;
            split_bf16(av.x, h0.x, l0.x);
            split_bf16(av.y, h0.y, l0.y);
            split_bf16(av.z, h1.x, l1.x);
            split_bf16(av.w, h1.y, l1.y);
            *(__nv_bfloat162*)&sAh[row][kl] = h0;
            *(__nv_bfloat162*)&sAh[row][kl + 2] = h1;
            *(__nv_bfloat162*)&sAl[row][kl] = l0;
            *(__nv_bfloat162*)&sAl[row][kl + 2] = l1;
        }
        // fill B: 128 rows x 4 uint4 (8 bf16 each)
        for (int idx = tid; idx < 128 * 4; idx += 256) {
            int row = idx >> 2;
            int kl = (idx & 3) << 3;
            size_t go = (size_t)(n0 + row) * K_PAD + kc * BK + kl;
            *(uint4*)&sBh[row][kl] = *(const uint4*)(Bhi + go);
            *(uint4*)&sBl[row][kl] = *(const uint4*)(Blo + go);
        }
        __syncthreads();

#pragma unroll
        for (int ks = 0; ks < 2; ks++) {
            int k0 = ks * 16;
            uint32_t ah[2][4], al[2][4];
#pragma unroll
            for (int mi = 0; mi < 2; mi++) {
                int r = wm + mi * 16 + (lane & 15);
                int c = k0 + ((lane >> 4) << 3);
                LDM4(ah[mi][0], ah[mi][1], ah[mi][2], ah[mi][3], smem_u32(&sAh[r][c]));
                LDM4(al[mi][0], al[mi][1], al[mi][2], al[mi][3], smem_u32(&sAl[r][c]));
            }
            uint32_t bh[4][4], bl[4][4];
#pragma unroll
            for (int nb = 0; nb < 4; nb++) {
                int r = wn + nb * 16 + (lane & 7) + ((lane >> 4) << 3);
                int c = k0 + (((lane >> 3) & 1) << 3);
                LDM4(bh[nb][0], bh[nb][1], bh[nb][2], bh[nb][3], smem_u32(&sBh[r][c]));
                LDM4(bl[nb][0], bl[nb][1], bl[nb][2], bl[nb][3], smem_u32(&sBl[r][c]));
            }
#pragma unroll
            for (int mi = 0; mi < 2; mi++)
#pragma unroll
                for (int nb = 0; nb < 4; nb++) {
                    MMA16816(acc[mi][nb * 2 + 0], ah[mi], bh[nb][0], bh[nb][1]);
                    MMA16816(acc[mi][nb * 2 + 0], ah[mi], bl[nb][0], bl[nb][1]);
                    MMA16816(acc[mi][nb * 2 + 0], al[mi], bh[nb][0], bh[nb][1]);
                    MMA16816(acc[mi][nb * 2 + 1], ah[mi], bh[nb][2], bh[nb][3]);
                    MMA16816(acc[mi][nb * 2 + 1], ah[mi], bl[nb][2], bl[nb][3]);
                    MMA16816(acc[mi][nb * 2 + 1], al[mi], bh[nb][2], bh[nb][3]);
                }
        }
        __syncthreads();
    }

    // ---- epilogue ----
#pragma unroll
    for (int mi = 0; mi < 2; mi++) {
        int gm0 = m0 + wm + mi * 16 + (lane >> 2);
        int gm1 = gm0 + 8;
        bool mu0 = false, mt0 = false, mu1 = false, mt1 = false;
        if (epi_mode == 1) {
            if (gm0 < M) { mu0 = g_deg_u[gm0] > 0; mt0 = g_deg_t[gm0] > 0; }
            if (gm1 < M) { mu1 = g_deg_u[gm1] > 0; mt1 = g_deg_t[gm1] > 0; }
        }
#pragma unroll
        for (int ni = 0; ni < 8; ni++) {
            int gn = n0 + wn + ni * 8 + ((lane & 3) << 1);
            float v00 = acc[mi][ni][0], v01 = acc[mi][ni][1];
            float v10 = acc[mi][ni][2], v11 = acc[mi][ni][3];
            if (epi_mode == 1) {
                float bs0 = g_bsum[gn], bs1 = g_bsum[gn + 1];
                float u0 = g_bu[gn], u1 = g_bu[gn + 1];
                float l0 = g_bl[gn], l1 = g_bl[gn + 1];
                v00 += bs0 + (mu0 ? u0 : 0.f) + (mt0 ? l0 : 0.f);
                v01 += bs1 + (mu0 ? u1 : 0.f) + (mt0 ? l1 : 0.f);
                v10 += bs0 + (mu1 ? u0 : 0.f) + (mt1 ? l0 : 0.f);
                v11 += bs1 + (mu1 ? u1 : 0.f) + (mt1 ? l1 : 0.f);
            } else if (epi_mode == 2) {
                float b0 = bias_ext[gn], b1 = bias_ext[gn + 1];
                v00 += b0; v01 += b1; v10 += b0; v11 += b1;
            } else {
                if (gm0 < M) {
                    const float2 cv = *(const float2*)(g_const + (size_t)gm0 * 384 + coff + gn);
                    v00 += cv.x; v01 += cv.y;
                }
                if (gm1 < M) {
                    const float2 cv = *(const float2*)(g_const + (size_t)gm1 * 384 + coff + gn);
                    v10 += cv.x; v11 += cv.y;
                }
                v00 *= alpha; v01 *= alpha; v10 *= alpha; v11 *= alpha;
                if (relu) {
                    v00 = fmaxf(v00, 0.f); v01 = fmaxf(v01, 0.f);
                    v10 = fmaxf(v10, 0.f); v11 = fmaxf(v11, 0.f);
                }
            }
            if (gm0 < M) *(float2*)(C + (size_t)gm0 * ldc + gn) = make_float2(v00, v01);
            if (gm1 < M) *(float2*)(C + (size_t)gm1 * ldc + gn) = make_float2(v10, v11);
        }
    }
}

// ---------------- launch (pure kernel launches; no other CUDA API) ----------------
extern "C" void kernel_launch(void* const* d_in, const int* in_sizes, int n_in,
                              void* d_out, int out_size) {
    const float* feat_s = (const float*)d_in[0];
    const float* feat_c = (const float*)d_in[1];
    const float* feat_l = (const float*)d_in[2];
    const float* W_fs = (const float*)d_in[3];
    const float* b_fs = (const float*)d_in[4];
    const float* W_fc = (const float*)d_in[5];
    const float* b_fc = (const float*)d_in[6];
    const float* W_fl = (const float*)d_in[7];
    const float* b_fl = (const float*)d_in[8];
    const float* W_self_u = (const float*)d_in[9];
    const float* W_neigh_u = (const float*)d_in[10];
    const float* b_u = (const float*)d_in[11];
    const float* W_self_t = (const float*)d_in[12];
    const float* W_neigh_t = (const float*)d_in[13];
    const float* b_t = (const float*)d_in[14];
    const int* und_src = (const int*)d_in[15];
    const int* und_dst = (const int*)d_in[16];
    const int* tea_src = (const int*)d_in[17];
    const int* tea_dst = (const int*)d_in[18];
    float* out = (float*)d_out;

    const int MT = (N_C + 127) / 128;  // 157 row tiles

    zero_deg_kernel<<<(N_C + 255) / 256, 256>>>();
    {
        int total = 384 * 192 + 384 * 3 + NLAY * 128 * 128 + 128 * 64;
        prep_kernel<<<(total + 255) / 256, 256>>>(W_fs, b_fs, W_fl, b_fl,
                                                  W_self_u, W_neigh_u, b_u,
                                                  W_self_t, W_neigh_t, b_t, W_fc);
    }
    hist_all_kernel<<<((E_U + E_T) / 4 + 255) / 256, 256>>>((const int4*)und_dst, (const int4*)tea_dst);
    {
        dim3 g(NBLK, 2);
        scan_part_kernel<<<g, 256>>>();
        scan_mid_kernel<<<1, 32>>>();
        // proj: hcA = feat_c @ W_fc + b_fc   (K=32, B padded to 64)
        mma_gemm_kernel<<<dim3(MT, 1), 256>>>(
            TAG_EXT, feat_c, D_C, 32, 64,
            TAG_BP, 0,
            TAG_HCA, nullptr, HDIM, N_C,
            /*epi*/2, b_fc, 0, 1.f, 0);
        scan_emit_kernel<<<g, 256>>>();
    }
    scatter_all_kernel<<<((E_U + E_T) / 4 + 255) / 256, 256>>>(
        (const int4*)und_src, (const int4*)und_dst, (const int4*)tea_src, (const int4*)tea_dst);

    agg_all_kernel<<<(2 * N_C * 32 + 255) / 256, 256>>>(feat_s, feat_l);

    // const[20000,384] = mf @ WfusedT^T + masked biases (K=192)
    mma_gemm_kernel<<<dim3(MT, 3), 256>>>(
        TAG_MF, nullptr, 192, 192, 192,
        TAG_BF, 0,
        TAG_CONST, nullptr, 384, N_C,
        /*epi*/1, nullptr, 0, 1.f, 0);

    // layers: hc_next = act(alpha_i * (hc @ Ws_i + const_i))   (K=128)
    for (int li = 0; li < NLAY; li++) {
        int a_tag = (li & 1) ? TAG_HCB : TAG_HCA;
        int c_tag = (li == NLAY - 1) ? TAG_EXT : ((li & 1) ? TAG_HCA : TAG_HCB);
        float* c_ext = (li == NLAY - 1) ? out : nullptr;
        float alpha = (li == 0) ? 0.5f : 1.0f;
        int relu = (li < NLAY - 1) ? 1 : 0;
        mma_gemm_kernel<<<dim3(MT, 1), 256>>>(
            a_tag, nullptr, HDIM, 128, 128,
            TAG_BW, li * 128 * 128,
            c_tag, c_ext, HDIM, N_C,
            /*epi*/0, nullptr, li * HDIM, alpha, relu);
    }
}

// round 10
// speedup vs baseline: 1.2135x; 1.2135x over previous
#include <cuda_runtime.h>
#include <cuda_bf16.h>

#define N_S 100000
#define N_C 20000
#define N_L 5000
#define E_U 2000000
#define E_T 500000
#define D_S 64
#define D_C 32
#define D_L 128
#define HDIM 128
#define NLAY 3

#define SCAN_ELEMS 1024
#define NBLK ((N_C + SCAN_ELEMS - 1) / SCAN_ELEMS)   // 20

// ---------------- scratch (static __device__ allocations only) ----------------
__device__ int   g_deg_u[N_C];
__device__ int   g_deg_t[N_C];
__device__ int   g_rp_u[N_C + 1];
__device__ int   g_rp_t[N_C + 1];
__device__ int   g_cur_u[N_C];
__device__ int   g_cur_t[N_C];
__device__ int   g_csr_u[E_U];
__device__ int   g_csr_t[E_T];
__device__ int   g_blksum[2][NBLK];
__device__ int   g_blkoff[2][NBLK];
__device__ float g_mf[N_C * 192];        // [c][0:64]=mean student feat, [64:192]=mean lecture feat
__device__ float g_Wfused[192 * 384];    // rows 0:64 = W_fs@Wnu_i ; rows 64:192 = W_fl@Wnt_i
__device__ float g_bu[384];              // b_fs @ Wnu_i  (applies when deg_u>0)
__device__ float g_bl[384];              // b_fl @ Wnt_i  (applies when deg_t>0)
__device__ float g_bsum[384];            // b_u[i] + b_t[i]
__device__ float g_Ws[NLAY * HDIM * HDIM];   // W_self_u[i] + W_self_t[i]
__device__ float g_const[N_C * 384];     // per-layer constant terms
__device__ float g_hcA[N_C * HDIM];
__device__ float g_hcB[N_C * HDIM];

// buffer tags (resolved on device; keeps kernel_launch free of cudaGetSymbolAddress)
#define TAG_EXT   0
#define TAG_MF    1
#define TAG_WF    2
#define TAG_CONST 3
#define TAG_HCA   4
#define TAG_HCB   5
#define TAG_WS    6

__device__ __forceinline__ const float* resolve_c(int tag, const float* ext, int off) {
    switch (tag) {
        case TAG_MF:    return g_mf;
        case TAG_WF:    return g_Wfused;
        case TAG_CONST: return g_const;
        case TAG_HCA:   return g_hcA;
        case TAG_HCB:   return g_hcB;
        case TAG_WS:    return g_Ws + off;
        default:        return ext + off;
    }
}
__device__ __forceinline__ float* resolve_m(int tag, float* ext) {
    switch (tag) {
        case TAG_CONST: return g_const;
        case TAG_HCA:   return g_hcA;
        case TAG_HCB:   return g_hcB;
        default:        return ext;
    }
}

// ---------------- CSR build ----------------
__global__ void zero_deg_kernel() {
    int i = blockIdx.x * blockDim.x + threadIdx.x;
    if (i < N_C) { g_deg_u[i] = 0; g_deg_t[i] = 0; }
}

// 4 edges per thread (int4)
__global__ void hist_all_kernel(const int4* __restrict__ und_dst, const int4* __restrict__ tea_dst) {
    int i = blockIdx.x * blockDim.x + threadIdx.x;
    if (i < E_U / 4) {
        int4 d = und_dst[i];
        atomicAdd(&g_deg_u[d.x], 1);
        atomicAdd(&g_deg_u[d.y], 1);
        atomicAdd(&g_deg_u[d.z], 1);
        atomicAdd(&g_deg_u[d.w], 1);
    } else {
        int j = i - E_U / 4;
        if (j < E_T / 4) {
            int4 d = tea_dst[j];
            atomicAdd(&g_deg_t[d.x], 1);
            atomicAdd(&g_deg_t[d.y], 1);
            atomicAdd(&g_deg_t[d.z], 1);
            atomicAdd(&g_deg_t[d.w], 1);
        }
    }
}

// phase 1: per-block partial sums. grid (NBLK, 2)
__global__ void scan_part_kernel() {
    int rel = blockIdx.y;
    const int* deg = rel ? g_deg_t : g_deg_u;
    int tid = threadIdx.x;
    int base = blockIdx.x * SCAN_ELEMS + tid * 4;
    int s = 0;
#pragma unroll
    for (int j = 0; j < 4; j++)
        if (base + j < N_C) s += deg[base + j];
    __shared__ int sh[256];
    sh[tid] = s;
    __syncthreads();
    for (int off = 128; off > 0; off >>= 1) {
        if (tid < off) sh[tid] += sh[tid + off];
        __syncthreads();
    }
    if (tid == 0) g_blksum[rel][blockIdx.x] = sh[0];
}

// phase 2: scan NBLK block sums per relation (tiny)
__global__ void scan_mid_kernel() {
    int tid = threadIdx.x;
    if (tid < 2) {
        int run = 0;
        for (int b = 0; b < NBLK; b++) {
            g_blkoff[tid][b] = run;
            run += g_blksum[tid][b];
        }
        if (tid) g_rp_t[N_C] = run; else g_rp_u[N_C] = run;
    }
}

// phase 3: emit rowptr + cur. grid (NBLK, 2)
__global__ void scan_emit_kernel() {
    int rel = blockIdx.y;
    const int* deg = rel ? g_deg_t : g_deg_u;
    int* rowptr = rel ? g_rp_t : g_rp_u;
    int* cur = rel ? g_cur_t : g_cur_u;
    int tid = threadIdx.x;
    int base = blockIdx.x * SCAN_ELEMS + tid * 4;
    int v[4];
    int s = 0;
#pragma unroll
    for (int j = 0; j < 4; j++) {
        v[j] = (base + j < N_C) ? deg[base + j] : 0;
        s += v[j];
    }
    __shared__ int sh[256];
    sh[tid] = s;
    __syncthreads();
    for (int off = 1; off < 256; off <<= 1) {
        int t = (tid >= off) ? sh[tid - off] : 0;
        __syncthreads();
        sh[tid] += t;
        __syncthreads();
    }
    int excl = ((tid > 0) ? sh[tid - 1] : 0) + g_blkoff[rel][blockIdx.x];
#pragma unroll
    for (int j = 0; j < 4; j++) {
        if (base + j < N_C) {
            rowptr[base + j] = excl;
            cur[base + j] = excl;
            excl += v[j];
        }
    }
}

// 4 edges per thread (int4)
__global__ void scatter_all_kernel(const int4* __restrict__ und_src, const int4* __restrict__ und_dst,
                                   const int4* __restrict__ tea_src, const int4* __restrict__ tea_dst) {
    int i = blockIdx.x * blockDim.x + threadIdx.x;
    if (i < E_U / 4) {
        int4 d = und_dst[i];
        int4 s = und_src[i];
        g_csr_u[atomicAdd(&g_cur_u[d.x], 1)] = s.x;
        g_csr_u[atomicAdd(&g_cur_u[d.y], 1)] = s.y;
        g_csr_u[atomicAdd(&g_cur_u[d.z], 1)] = s.z;
        g_csr_u[atomicAdd(&g_cur_u[d.w], 1)] = s.w;
    } else {
        int j = i - E_U / 4;
        if (j < E_T / 4) {
            int4 d = tea_dst[j];
            int4 s = tea_src[j];
            g_csr_t[atomicAdd(&g_cur_t[d.x], 1)] = s.x;
            g_csr_t[atomicAdd(&g_cur_t[d.y], 1)] = s.y;
            g_csr_t[atomicAdd(&g_cur_t[d.z], 1)] = s.z;
            g_csr_t[atomicAdd(&g_cur_t[d.w], 1)] = s.w;
        }
    }
}

// ---------------- aggregation: warp per concept, both relations in one grid ----------------
__global__ void agg_all_kernel(const float* __restrict__ feat_s, const float* __restrict__ feat_l) {
    int w = (blockIdx.x * blockDim.x + threadIdx.x) >> 5;
    int lane = threadIdx.x & 31;
    if (w < N_C) {
        int s0 = g_rp_u[w], s1 = g_rp_u[w + 1];
        float2 a0 = {0.f, 0.f}, a1 = {0.f, 0.f}, a2 = {0.f, 0.f}, a3 = {0.f, 0.f};
        int e = s0;
        for (; e + 4 <= s1; e += 4) {
            int i0 = g_csr_u[e], i1 = g_csr_u[e + 1], i2 = g_csr_u[e + 2], i3 = g_csr_u[e + 3];
            float2 v0 = __ldg((const float2*)(feat_s + (size_t)i0 * D_S) + lane);
            float2 v1 = __ldg((const float2*)(feat_s + (size_t)i1 * D_S) + lane);
            float2 v2 = __ldg((const float2*)(feat_s + (size_t)i2 * D_S) + lane);
            float2 v3 = __ldg((const float2*)(feat_s + (size_t)i3 * D_S) + lane);
            a0.x += v0.x; a0.y += v0.y;
            a1.x += v1.x; a1.y += v1.y;
            a2.x += v2.x; a2.y += v2.y;
            a3.x += v3.x; a3.y += v3.y;
        }
        for (; e < s1; e++) {
            int i0 = g_csr_u[e];
            float2 v0 = __ldg((const float2*)(feat_s + (size_t)i0 * D_S) + lane);
            a0.x += v0.x; a0.y += v0.y;
        }
        float sx = a0.x + a1.x + a2.x + a3.x;
        float sy = a0.y + a1.y + a2.y + a3.y;
        float inv = 1.0f / (float)max(s1 - s0, 1);
        g_mf[(size_t)w * 192 + lane * 2 + 0] = sx * inv;
        g_mf[(size_t)w * 192 + lane * 2 + 1] = sy * inv;
    } else if (w < 2 * N_C) {
        int c = w - N_C;
        int s0 = g_rp_t[c], s1 = g_rp_t[c + 1];
        float4 a0 = {0, 0, 0, 0}, a1 = {0, 0, 0, 0};
        int e = s0;
        for (; e + 2 <= s1; e += 2) {
            int i0 = g_csr_t[e], i1 = g_csr_t[e + 1];
            float4 v0 = __ldg((const float4*)(feat_l + (size_t)i0 * D_L) + lane);
            float4 v1 = __ldg((const float4*)(feat_l + (size_t)i1 * D_L) + lane);
            a0.x += v0.x; a0.y += v0.y; a0.z += v0.z; a0.w += v0.w;
            a1.x += v1.x; a1.y += v1.y; a1.z += v1.z; a1.w += v1.w;
        }
        for (; e < s1; e++) {
            int i0 = g_csr_t[e];
            float4 v0 = __ldg((const float4*)(feat_l + (size_t)i0 * D_L) + lane);
            a0.x += v0.x; a0.y += v0.y; a0.z += v0.z; a0.w += v0.w;
        }
        float sx = a0.x + a1.x, sy = a0.y + a1.y, sz = a0.z + a1.z, sw = a0.w + a1.w;
        float inv = 1.0f / (float)max(s1 - s0, 1);
        float* o = g_mf + (size_t)c * 192 + 64 + lane * 4;
        o[0] = sx * inv; o[1] = sy * inv; o[2] = sz * inv; o[3] = sw * inv;
    }
}

// ---------------- fused weight prep (tiny) ----------------
__global__ void prep_kernel(const float* __restrict__ W_fs, const float* __restrict__ b_fs,
                            const float* __restrict__ W_fl, const float* __restrict__ b_fl,
                            const float* __restrict__ Wsu, const float* __restrict__ Wnu,
                            const float* __restrict__ bu_in,
                            const float* __restrict__ Wst, const float* __restrict__ Wnt,
                            const float* __restrict__ bt_in) {
    const int n0 = 64 * 384;
    const int n1 = 128 * 384;
    const int n2 = 384, n3 = 384, n4 = 384;
    const int n5 = NLAY * HDIM * HDIM;
    int idx = blockIdx.x * blockDim.x + threadIdx.x;
    if (idx < n0) {
        int r = idx / 384, c = idx % 384;
        int li = c >> 7, n = c & 127;
        const float* wn = Wnu + li * HDIM * HDIM;
        float s = 0.f;
        for (int k = 0; k < HDIM; k++) s += W_fs[r * HDIM + k] * wn[k * HDIM + n];
        g_Wfused[r * 384 + c] = s;
        return;
    }
    idx -= n0;
    if (idx < n1) {
        int r = idx / 384, c = idx % 384;
        int li = c >> 7, n = c & 127;
        const float* wn = Wnt + li * HDIM * HDIM;
        float s = 0.f;
        for (int k = 0; k < HDIM; k++) s += W_fl[r * HDIM + k] * wn[k * HDIM + n];
        g_Wfused[(64 + r) * 384 + c] = s;
        return;
    }
    idx -= n1;
    if (idx < n2) {
        int li = idx >> 7, n = idx & 127;
        const float* wn = Wnu + li * HDIM * HDIM;
        float s = 0.f;
        for (int k = 0; k < HDIM; k++) s += b_fs[k] * wn[k * HDIM + n];
        g_bu[idx] = s;
        return;
    }
    idx -= n2;
    if (idx < n3) {
        int li = idx >> 7, n = idx & 127;
        const float* wn = Wnt + li * HDIM * HDIM;
        float s = 0.f;
        for (int k = 0; k < HDIM; k++) s += b_fl[k] * wn[k * HDIM + n];
        g_bl[idx] = s;
        return;
    }
    idx -= n3;
    if (idx < n4) {
        g_bsum[idx] = bu_in[idx] + bt_in[idx];
        return;
    }
    idx -= n4;
    if (idx < n5) {
        g_Ws[idx] = Wsu[idx] + Wst[idx];
        return;
    }
}

// ---------------- tiled SIMT GEMM (R2/R4-proven): 128x64 tile, 8x4/thread ----------------
// epi_mode: 0 = none, 1 = const-build (bsum + deg-masked bu/bl), 2 = external bias
__global__ __launch_bounds__(256) void gemm_kernel(
    int a_tag, const float* a_ext, int lda,
    int b_tag, const float* b_ext, int b_off, int ldb,
    int c_tag, float* c_ext, int ldc,
    int M, int N, int K,
    int epi_mode, const float* bias_ext,
    int use_cbuf, int coff,
    float alpha, int relu) {
    const float* A = resolve_c(a_tag, a_ext, 0);
    const float* B = resolve_c(b_tag, b_ext, b_off);
    float* C = resolve_m(c_tag, c_ext);

    __shared__ float As[8][132];
    __shared__ float Bs[8][68];
    int tid = threadIdx.x;
    int m0 = blockIdx.x * 128;
    int n0 = blockIdx.y * 64;
    int tx = tid & 15;
    int ty = tid >> 4;

    float acc[8][4];
#pragma unroll
    for (int i = 0; i < 8; i++)
#pragma unroll
        for (int j = 0; j < 4; j++) acc[i][j] = 0.f;

    int la_row = tid >> 1;
    int la_k = (tid & 1) * 4;
    int lb_k = tid >> 5;
    int lb_n = (tid & 31) * 2;

    for (int k0 = 0; k0 < K; k0 += 8) {
        float4 av = {0.f, 0.f, 0.f, 0.f};
        int gm = m0 + la_row;
        if (gm < M) av = *(const float4*)(A + (size_t)gm * lda + k0 + la_k);
        As[la_k + 0][la_row] = av.x;
        As[la_k + 1][la_row] = av.y;
        As[la_k + 2][la_row] = av.z;
        As[la_k + 3][la_row] = av.w;
        float2 bv = *(const float2*)(B + (size_t)(k0 + lb_k) * ldb + n0 + lb_n);
        Bs[lb_k][lb_n] = bv.x;
        Bs[lb_k][lb_n + 1] = bv.y;
        __syncthreads();
#pragma unroll
        for (int kk = 0; kk < 8; kk++) {
            float4 a0 = *(const float4*)&As[kk][ty * 8];
            float4 a1 = *(const float4*)&As[kk][ty * 8 + 4];
            float4 b = *(const float4*)&Bs[kk][tx * 4];
            float a[8] = {a0.x, a0.y, a0.z, a0.w, a1.x, a1.y, a1.z, a1.w};
            float bb[4] = {b.x, b.y, b.z, b.w};
#pragma unroll
            for (int i = 0; i < 8; i++)
#pragma unroll
                for (int j = 0; j < 4; j++) acc[i][j] += a[i] * bb[j];
        }
        __syncthreads();
    }

#pragma unroll
    for (int i = 0; i < 8; i++) {
        int gm = m0 + ty * 8 + i;
        if (gm >= M) break;
        bool mu = false, mt = false;
        if (epi_mode == 1) {
            mu = (g_deg_u[gm] > 0);
            mt = (g_deg_t[gm] > 0);
        }
        float res[4];
#pragma unroll
        for (int j = 0; j < 4; j++) {
            int gn = n0 + tx * 4 + j;
            float v = acc[i][j];
            if (epi_mode == 1) {
                v += g_bsum[gn];
                if (mu) v += g_bu[gn];
                if (mt) v += g_bl[gn];
            } else if (epi_mode == 2) {
                v += bias_ext[gn];
            }
            if (use_cbuf) v += g_const[(size_t)gm * 384 + coff + gn];
            v *= alpha;
            if (relu) v = fmaxf(v, 0.f);
            res[j] = v;
        }
        *(float4*)(C + (size_t)gm * ldc + n0 + tx * 4) = make_float4(res[0], res[1], res[2], res[3]);
    }
}

// ---------------- launch (pure kernel launches; no other CUDA API) ----------------
extern "C" void kernel_launch(void* const* d_in, const int* in_sizes, int n_in,
                              void* d_out, int out_size) {
    const float* feat_s = (const float*)d_in[0];
    const float* feat_c = (const float*)d_in[1];
    const float* feat_l = (const float*)d_in[2];
    const float* W_fs = (const float*)d_in[3];
    const float* b_fs = (const float*)d_in[4];
    const float* W_fc = (const float*)d_in[5];
    const float* b_fc = (const float*)d_in[6];
    const float* W_fl = (const float*)d_in[7];
    const float* b_fl = (const float*)d_in[8];
    const float* W_self_u = (const float*)d_in[9];
    const float* W_neigh_u = (const float*)d_in[10];
    const float* b_u = (const float*)d_in[11];
    const float* W_self_t = (const float*)d_in[12];
    const float* W_neigh_t = (const float*)d_in[13];
    const float* b_t = (const float*)d_in[14];
    const int* und_src = (const int*)d_in[15];
    const int* und_dst = (const int*)d_in[16];
    const int* tea_src = (const int*)d_in[17];
    const int* tea_dst = (const int*)d_in[18];
    float* out = (float*)d_out;

    // 1. CSR build
    zero_deg_kernel<<<(N_C + 255) / 256, 256>>>();
    hist_all_kernel<<<((E_U + E_T) / 4 + 255) / 256, 256>>>((const int4*)und_dst, (const int4*)tea_dst);
    {
        dim3 g(NBLK, 2);
        scan_part_kernel<<<g, 256>>>();
        scan_mid_kernel<<<1, 32>>>();
        scan_emit_kernel<<<g, 256>>>();
    }
    scatter_all_kernel<<<((E_U + E_T) / 4 + 255) / 256, 256>>>(
        (const int4*)und_src, (const int4*)und_dst, (const int4*)tea_src, (const int4*)tea_dst);

    // 2. segment means of RAW features (constant across layers)
    agg_all_kernel<<<(2 * N_C * 32 + 255) / 256, 256>>>(feat_s, feat_l);

    // 3. fold weights
    {
        int total = 64 * 384 + 128 * 384 + 384 * 3 + NLAY * HDIM * HDIM;
        prep_kernel<<<(total + 255) / 256, 256>>>(W_fs, b_fs, W_fl, b_fl,
                                                  W_self_u, W_neigh_u, b_u,
                                                  W_self_t, W_neigh_t, b_t);
    }

    // 4. layer-constant terms: const[20000,384] = mf @ Wfused + masked biases + bsum
    {
        dim3 grid((N_C + 127) / 128, 384 / 64);
        gemm_kernel<<<grid, 256>>>(TAG_MF, nullptr, 192,
                                   TAG_WF, nullptr, 0, 384,
                                   TAG_CONST, nullptr, 384,
                                   N_C, 384, 192,
                                   /*epi*/1, nullptr,
                                   /*cbuf*/0, 0, 1.f, 0);
    }

    // 5. input projection of concepts: hcA = feat_c @ W_fc + b_fc
    {
        dim3 grid((N_C + 127) / 128, HDIM / 64);
        gemm_kernel<<<grid, 256>>>(TAG_EXT, feat_c, D_C,
                                   TAG_EXT, W_fc, 0, HDIM,
                                   TAG_HCA, nullptr, HDIM,
                                   N_C, HDIM, D_C,
                                   /*epi*/2, b_fc,
                                   /*cbuf*/0, 0, 1.f, 0);
    }

    // 6. three layers: hc_next = act(alpha_i * (hc @ Ws_i + const_i))
    for (int li = 0; li < NLAY; li++) {
        int a_tag = (li & 1) ? TAG_HCB : TAG_HCA;
        int c_tag = (li == NLAY - 1) ? TAG_EXT : ((li & 1) ? TAG_HCA : TAG_HCB);
        float* c_ext = (li == NLAY - 1) ? out : nullptr;
        float alpha = (li == 0) ? 0.5f : 1.0f;
        int relu = (li < NLAY - 1) ? 1 : 0;
        dim3 grid((N_C + 127) / 128, HDIM / 64);
        gemm_kernel<<<grid, 256>>>(a_tag, nullptr, HDIM,
                                   TAG_WS, nullptr, li * HDIM * HDIM, HDIM,
                                   c_tag, c_ext, HDIM,
                                   N_C, HDIM, HDIM,
                                   /*epi*/0, nullptr,
                                   /*cbuf*/1, li * HDIM,
                                   alpha, relu);
    }
}